// round 5
// baseline (speedup 1.0000x reference)
#include <cuda_runtime.h>
#include <cstdint>
#include <cstddef>

#define Bsz 256
#define Tt  512
#define DIN 32
#define Hh  128
#define LATD 64
#define Gg  512   // 4*H

// Scratch (static __device__ — no allocations allowed)
__device__ float g_xg [(size_t)Bsz * Tt * Gg];   // 256 MB: x @ Wih^T + bih + bhh
__device__ float g_hs2[(size_t)Bsz * Tt * Hh];   // 64 MB : decoder hidden states

typedef unsigned long long u64;

__device__ __forceinline__ void fma2(u64& d, u64 a, u64 b) {
    asm("fma.rn.f32x2 %0, %1, %2, %0;" : "+l"(d) : "l"(a), "l"(b));
}
__device__ __forceinline__ float lo2(u64 v) { return __uint_as_float((unsigned)(v & 0xffffffffu)); }
__device__ __forceinline__ float hi2(u64 v) { return __uint_as_float((unsigned)(v >> 32)); }

__device__ __forceinline__ float sigm(float x)   { return __fdividef(1.f, 1.f + __expf(-x)); }
__device__ __forceinline__ float tanh_f(float x) { return __fdividef(2.f, 1.f + __expf(-2.f * x)) - 1.f; }

// ---------------------------------------------------------------------------
// Kernel A: g_xg[b,t,j] = sum_d x[b,t,d]*Wih[j,d] + bih[j] + bhh[j]
// ---------------------------------------------------------------------------
__global__ __launch_bounds__(512) void xg_kernel(
    const float* __restrict__ x, const float* __restrict__ Wih,
    const float* __restrict__ bih, const float* __restrict__ bhh)
{
    const int j = threadIdx.x;
    const size_t row0 = (size_t)blockIdx.x * 128;
    __shared__ float xs[128 * DIN];   // 16 KB

    const float4* src = (const float4*)(x + row0 * DIN);
    float4* dst = (float4*)xs;
    for (int i = j; i < 128 * DIN / 4; i += 512) dst[i] = src[i];

    u64 w[16];
    const u64* wr = (const u64*)(Wih + j * DIN);
    #pragma unroll
    for (int p = 0; p < 16; p++) w[p] = wr[p];
    float bias = __ldg(bih + j) + __ldg(bhh + j);
    __syncthreads();

    for (int r = 0; r < 128; r++) {
        u64 acc = 0;
        const u64* xp = (const u64*)(xs + r * DIN);
        #pragma unroll
        for (int p = 0; p < 16; p++) fma2(acc, w[p], xp[p]);
        g_xg[(row0 + r) * Gg + j] = lo2(acc) + hi2(acc) + bias;
    }
}

// ---------------------------------------------------------------------------
// Recurrent LSTM kernel, software-pipelined over the CTA's two independent
// batch rows (groups A=b0, B=b0+1). 128 CTAs x 256 threads.
// Thread j owns gate rows j and j+256; k=[0,108) in registers (216 regs),
// k=[108,128) in smem. Each half-step computes one group's gates while the
// OTHER group's combine (c/h update, tanh chain) rides along in the same
// instruction stream — its latency hides under the 128-fma2 block.
// ---------------------------------------------------------------------------
template<bool DEC>
__global__ __launch_bounds__(256, 1) void lstm_kernel(
    const float* __restrict__ Whh,      // [512,128]
    const float* __restrict__ Wih,      // DEC: [512,64]
    const float* __restrict__ bih, const float* __restrict__ bhh,  // DEC only
    const float* __restrict__ enc_in,   // DEC: encoded [B,64]
    const float* __restrict__ Wl,  const float* __restrict__ bl,   // ENC: enc_Wl/enc_bl
    float* __restrict__ out)            // ENC: encoded out [B,64]
{
    __shared__ __align__(16) ulonglong2 WsmA[5 * 256];  // rows j,     k=108..127 (20 KB)
    __shared__ __align__(16) ulonglong2 WsmB[5 * 256];  // rows j+256  (20 KB)
    __shared__ __align__(16) float hAs[128];
    __shared__ __align__(16) float hBs[128];
    __shared__ float gbA[512], gbB[512];
    __shared__ float xb[128];

    const int j  = threadIdx.x;
    const int b0 = blockIdx.x * 2;

    float xgA0 = 0.f, xgA1 = 0.f, xgB0 = 0.f, xgB1 = 0.f;  // DEC: t-invariant
    const float* pxA = nullptr; const float* pxB = nullptr;

    if (DEC) {
        if (j < 128) xb[j] = enc_in[b0 * LATD + j];
        __syncthreads();
        float s00 = 0.f, s01 = 0.f, s10 = 0.f, s11 = 0.f;
        const float* wiA = Wih + j * LATD;
        const float* wiB = Wih + (j + 256) * LATD;
        #pragma unroll 8
        for (int d = 0; d < LATD; d++) {
            float wa = __ldg(wiA + d), wb = __ldg(wiB + d);
            float x0 = xb[d], x1 = xb[64 + d];
            s00 += wa * x0; s01 += wb * x0;
            s10 += wa * x1; s11 += wb * x1;
        }
        float bA = __ldg(bih + j) + __ldg(bhh + j);
        float bB = __ldg(bih + j + 256) + __ldg(bhh + j + 256);
        xgA0 = s00 + bA; xgA1 = s01 + bB;   // group A (batch b0)
        xgB0 = s10 + bA; xgB1 = s11 + bB;   // group B (batch b0+1)
    } else {
        pxA = g_xg + (size_t)b0 * Tt * Gg + j;
        pxB = pxA + (size_t)Tt * Gg;
    }

    // Weights: k=[0,108) -> registers (54 u64-pairs per row), k=[108,128) -> smem
    const float* wrowA = Whh + j * Hh;
    const float* wrowB = Whh + (j + 256) * Hh;
    u64 wA[54], wB[54];
    #pragma unroll
    for (int p = 0; p < 54; p++) wA[p] = *(const u64*)(wrowA + 2 * p);
    #pragma unroll
    for (int p = 0; p < 54; p++) wB[p] = *(const u64*)(wrowB + 2 * p);
    #pragma unroll
    for (int q = 0; q < 5; q++) WsmA[q * 256 + j] = *(const ulonglong2*)(wrowA + 108 + 4 * q);
    #pragma unroll
    for (int q = 0; q < 5; q++) WsmB[q * 256 + j] = *(const ulonglong2*)(wrowB + 108 + 4 * q);
    if (j < 128) { hAs[j] = 0.f; hBs[j] = 0.f; }
    __syncthreads();

    float cA = 0.f, cB = 0.f;

    // one half-step: gates for group X (+ overlapped combine of group Y)
    auto half = [&](const float* hX, float* gbX,
                    const float* px, float pg0, float pg1, int t,
                    bool comb, const float* gbY, float* hY, float& cY,
                    float* hs2p)
    {
        float xg0, xg1;
        if (DEC) { xg0 = pg0; xg1 = pg1; }
        else {
            const float* p2 = px + (size_t)t * Gg;
            xg0 = __ldg(p2); xg1 = __ldg(p2 + 256);
        }
        u64 a0 = 0, a1 = 0;
        const ulonglong2* hp = (const ulonglong2*)hX;
        #pragma unroll
        for (int p = 0; p < 27; p++) {
            ulonglong2 h4 = hp[p];
            fma2(a0, wA[2 * p], h4.x); fma2(a0, wA[2 * p + 1], h4.y);
            fma2(a1, wB[2 * p], h4.x); fma2(a1, wB[2 * p + 1], h4.y);
        }
        #pragma unroll
        for (int q = 0; q < 5; q++) {
            ulonglong2 h4 = hp[27 + q];
            ulonglong2 wa = WsmA[q * 256 + j];
            ulonglong2 wb = WsmB[q * 256 + j];
            fma2(a0, wa.x, h4.x); fma2(a0, wa.y, h4.y);
            fma2(a1, wb.x, h4.x); fma2(a1, wb.y, h4.y);
        }
        // overlapped combine for the OTHER group (latency hides under fma above)
        if (comb && j < 128) {
            float iv = gbY[j], fv = gbY[128 + j], gv = gbY[256 + j], ov = gbY[384 + j];
            cY = fv * cY + iv * gv;
            float h = ov * tanh_f(cY);
            hY[j] = h;
            if (DEC) hs2p[j] = h;
        }
        float v0 = lo2(a0) + hi2(a0) + xg0;   // gate row j    : i (j<128) / f
        float v1 = lo2(a1) + hi2(a1) + xg1;   // gate row j+256: g (j<128) / o
        v0 = sigm(v0);
        v1 = (j < 128) ? tanh_f(v1) : sigm(v1);
        gbX[j] = v0; gbX[256 + j] = v1;
        __syncthreads();
    };

    float* hs2A = DEC ? (g_hs2 + (size_t)b0 * Tt * Hh) : (float*)nullptr;
    float* hs2B = DEC ? (g_hs2 + (size_t)(b0 + 1) * Tt * Hh) : (float*)nullptr;

    // prologue: A(0) without combine; B(0) combining A(0)
    half(hAs, gbA, pxA, xgA0, xgA1, 0, false, gbB, hBs, cB, nullptr);
    half(hBs, gbB, pxB, xgB0, xgB1, 0, true,  gbA, hAs, cA, hs2A);
    for (int t = 1; t < Tt; t++) {
        half(hAs, gbA, pxA, xgA0, xgA1, t, true, gbB, hBs, cB,
             DEC ? hs2B + (size_t)(t - 1) * Hh : nullptr);
        half(hBs, gbB, pxB, xgB0, xgB1, t, true, gbA, hAs, cA,
             DEC ? hs2A + (size_t)t * Hh : nullptr);
    }
    // drain: combine B(511)
    if (j < 128) {
        float iv = gbB[j], fv = gbB[128 + j], gv = gbB[256 + j], ov = gbB[384 + j];
        cB = fv * cB + iv * gv;
        float h = ov * tanh_f(cB);
        hBs[j] = h;
        if (DEC) hs2B[(size_t)(Tt - 1) * Hh + j] = h;
    }
    __syncthreads();

    if (!DEC) {
        // encoded = h_last @ enc_Wl^T + enc_bl  (64 outs x 2 rows)
        if (j < 128) {
            int rr = j >> 6, l = j & 63;
            const float* hsrc = rr ? hBs : hAs;
            const float* wlr = Wl + l * Hh;
            float acc = __ldg(bl + l);
            #pragma unroll 16
            for (int k = 0; k < Hh; k++) acc += __ldg(wlr + k) * hsrc[k];
            out[(b0 + rr) * LATD + l] = acc;
        }
    }
}

// ---------------------------------------------------------------------------
// Kernel D: decoded[b,t,d] = sum_h g_hs2[b,t,h]*dec_Wl[d,h] + dec_bl[d]
// grid 2048 x 256. W transposed to [kpair][d] u64 layout: per-lane loads span
// all 32 banks (2 wf, conflict-free); h read as u64 broadcast (1 wf).
// ---------------------------------------------------------------------------
__global__ __launch_bounds__(256) void out_kernel(
    const float* __restrict__ Wl, const float* __restrict__ bl,
    float* __restrict__ out)
{
    __shared__ __align__(16) float hrow[64 * 128];   // 32 KB
    __shared__ __align__(16) u64 wlT2[64 * 32];      // 16 KB : [kp][d] pairs
    const int t = threadIdx.x;
    const size_t row0 = (size_t)blockIdx.x * 64;

    {
        const float4* src = (const float4*)(g_hs2 + row0 * Hh);
        float4* dst = (float4*)hrow;
        #pragma unroll
        for (int i = t; i < 64 * 128 / 4; i += 256) dst[i] = src[i];
        // transpose Wl [32 d][128 k] -> wlT2 [64 kp][32 d] (u64 = k-pair)
        float* wf = (float*)wlT2;
        for (int i = t; i < 32 * 128; i += 256) {
            int d = i >> 7, k = i & 127;
            wf[(k >> 1) * 64 + d * 2 + (k & 1)] = Wl[i];
        }
    }
    __syncthreads();

    const int d  = t & 31;
    const int rb = t >> 5;   // warp-uniform -> hrow reads broadcast
    u64 acc[8];
    #pragma unroll
    for (int q = 0; q < 8; q++) acc[q] = 0;

    const u64* wp = wlT2 + d;
    const u64* h2 = (const u64*)hrow;
    #pragma unroll 8
    for (int kp = 0; kp < 64; kp++) {
        u64 w = wp[(size_t)kp * 32];
        #pragma unroll
        for (int q = 0; q < 8; q++)
            fma2(acc[q], w, h2[(rb + q * 8) * 64 + kp]);
    }
    float bias = __ldg(bl + d);
    #pragma unroll
    for (int q = 0; q < 8; q++)
        out[(row0 + rb + q * 8) * DIN + d] = lo2(acc[q]) + hi2(acc[q]) + bias;
}

// ---------------------------------------------------------------------------
extern "C" void kernel_launch(void* const* d_in, const int* in_sizes, int n_in,
                              void* d_out, int out_size)
{
    const float* x        = (const float*)d_in[0];
    const float* enc_Wih  = (const float*)d_in[1];
    const float* enc_Whh  = (const float*)d_in[2];
    const float* enc_bih  = (const float*)d_in[3];
    const float* enc_bhh  = (const float*)d_in[4];
    const float* enc_Wl   = (const float*)d_in[5];
    const float* enc_bl   = (const float*)d_in[6];
    const float* dec_Wih  = (const float*)d_in[7];
    const float* dec_Whh  = (const float*)d_in[8];
    const float* dec_bih  = (const float*)d_in[9];
    const float* dec_bhh  = (const float*)d_in[10];
    const float* dec_Wl   = (const float*)d_in[11];
    const float* dec_bl   = (const float*)d_in[12];
    float* out = (float*)d_out;

    // 1) input transform for encoder
    xg_kernel<<<(Bsz * Tt) / 128, 512>>>(x, enc_Wih, enc_bih, enc_bhh);
    // 2) encoder recurrence + encoded projection (writes out[0 : 256*64))
    lstm_kernel<false><<<Bsz / 2, 256>>>(
        enc_Whh, nullptr, nullptr, nullptr, nullptr, enc_Wl, enc_bl, out);
    // 3) decoder recurrence (reads encoded from out, writes g_hs2)
    lstm_kernel<true><<<Bsz / 2, 256>>>(
        dec_Whh, dec_Wih, dec_bih, dec_bhh, out, nullptr, nullptr, nullptr);
    // 4) decoded projection (writes out[256*64 : end))
    out_kernel<<<(Bsz * Tt) / 64, 256>>>(dec_Wl, dec_bl, out + Bsz * LATD);
}

// round 9
// speedup vs baseline: 1.2038x; 1.2038x over previous
#include <cuda_runtime.h>
#include <cstdint>
#include <cstddef>

#define Bsz 256
#define Tt  512
#define DIN 32
#define Hh  128
#define LATD 64
#define Gg  512   // 4*H

// Scratch (static __device__ — no allocations allowed)
__device__ float g_xg [(size_t)Bsz * Tt * Gg];   // permuted gate layout (see pos())
__device__ float g_hs2[(size_t)Bsz * Tt * Hh];   // decoder hidden states

typedef unsigned long long u64;

__device__ __forceinline__ void fma2(u64& d, u64 a, u64 b) {
    asm("fma.rn.f32x2 %0, %1, %2, %0;" : "+l"(d) : "l"(a), "l"(b));
}
__device__ __forceinline__ float lo2(u64 v) { return __uint_as_float((unsigned)(v & 0xffffffffu)); }
__device__ __forceinline__ float hi2(u64 v) { return __uint_as_float((unsigned)(v >> 32)); }

__device__ __forceinline__ float sigm(float x)   { return __fdividef(1.f, 1.f + __expf(-x)); }
__device__ __forceinline__ float tanh_f(float x) { return __fdividef(2.f, 1.f + __expf(-2.f * x)) - 1.f; }

// lstm thread j (e=j>>1, p=j&1) owns gate rows r0=e+128p and r1=256+e+128p.
// xg is stored so position j holds gate row r0(j), position 256+j holds r1(j):
// for original gate row r: pos(r) = (r>>8)*256 + (r&127)*2 + ((r>>7)&1).
__device__ __forceinline__ int xg_pos(int r) {
    return ((r >> 8) << 8) + ((r & 127) << 1) + ((r >> 7) & 1);
}

// ---------------------------------------------------------------------------
// Kernel A: g_xg[b,t,pos(j)] = sum_d x[b,t,d]*Wih[j,d] + bih[j] + bhh[j]
// ---------------------------------------------------------------------------
__global__ __launch_bounds__(512) void xg_kernel(
    const float* __restrict__ x, const float* __restrict__ Wih,
    const float* __restrict__ bih, const float* __restrict__ bhh)
{
    const int j = threadIdx.x;
    const int pos = xg_pos(j);
    const size_t row0 = (size_t)blockIdx.x * 128;
    __shared__ float xs[128 * DIN];   // 16 KB

    const float4* src = (const float4*)(x + row0 * DIN);
    float4* dst = (float4*)xs;
    for (int i = j; i < 128 * DIN / 4; i += 512) dst[i] = src[i];

    u64 w[16];
    const u64* wr = (const u64*)(Wih + j * DIN);
    #pragma unroll
    for (int p = 0; p < 16; p++) w[p] = wr[p];
    float bias = __ldg(bih + j) + __ldg(bhh + j);
    __syncthreads();

    for (int r = 0; r < 128; r++) {
        u64 acc = 0;
        const u64* xp = (const u64*)(xs + r * DIN);
        #pragma unroll
        for (int p = 0; p < 16; p++) fma2(acc, w[p], xp[p]);
        g_xg[(row0 + r) * Gg + pos] = lo2(acc) + hi2(acc) + bias;
    }
}

// ---------------------------------------------------------------------------
// Recurrent LSTM kernel. 128 CTAs x 256 threads, 2 batch rows per CTA.
// Thread j = (e, parity p): computes gate rows r0=e+128p (i/f) and
// r1=256+e+128p (g/o) for BOTH batch rows; k=[0,96) of each row in registers
// (192 regs), k=[96,128) in smem. Gates of element e live in lane pair
// (2e, 2e+1) -> combine via 4 shfl_xor(1), no gate smem, ONE barrier/step
// with double-buffered h. h interleaved: float4 m = (h0[2m],h0[2m+1],
// h1[2m],h1[2m+1]) so one LDS.128 broadcast feeds both batch rows.
// ---------------------------------------------------------------------------
#define W0_OFF   0
#define W1_OFF   32768
#define HB0_OFF  65536
#define HB1_OFF  66560
#define XB_OFF   67584
#define SMEM_BYTES 68096

template<bool DEC>
__global__ __launch_bounds__(256, 1) void lstm_kernel(
    const float* __restrict__ Whh,      // [512,128]
    const float* __restrict__ Wih,      // DEC: [512,64]
    const float* __restrict__ bih, const float* __restrict__ bhh,  // DEC only
    const float* __restrict__ enc_in,   // DEC: encoded [B,64]
    const float* __restrict__ Wl,  const float* __restrict__ bl,   // ENC
    float* __restrict__ out)            // ENC: encoded out [B,64]
{
    extern __shared__ char smem[];
    ulonglong2* Wsm0 = (ulonglong2*)(smem + W0_OFF);   // [8][256] row r0, k=96..127
    ulonglong2* Wsm1 = (ulonglong2*)(smem + W1_OFF);   // [8][256] row r1
    float* hb0 = (float*)(smem + HB0_OFF);             // 256 floats (interleaved)
    float* hb1 = (float*)(smem + HB1_OFF);
    float* xb  = (float*)(smem + XB_OFF);              // DEC: [2][64]

    const int j  = threadIdx.x;
    const int e  = j >> 1;
    const int p_ = j & 1;
    const int b0 = blockIdx.x * 2;
    const int r0 = e + 128 * p_;
    const int r1 = 256 + r0;

    float xg00 = 0.f, xg01 = 0.f, xg10 = 0.f, xg11 = 0.f;  // DEC: t-invariant
    const float* px0 = nullptr; const float* px1 = nullptr;

    if (DEC) {
        if (j < 128) xb[j] = enc_in[b0 * LATD + j];
        __syncthreads();
        const float* wi0 = Wih + r0 * LATD;
        const float* wi1 = Wih + r1 * LATD;
        #pragma unroll 8
        for (int d = 0; d < LATD; d++) {
            float w0 = __ldg(wi0 + d), w1 = __ldg(wi1 + d);
            float x0 = xb[d], x1 = xb[64 + d];
            xg00 += w0 * x0; xg01 += w0 * x1;
            xg10 += w1 * x0; xg11 += w1 * x1;
        }
        float bb0 = __ldg(bih + r0) + __ldg(bhh + r0);
        float bb1 = __ldg(bih + r1) + __ldg(bhh + r1);
        xg00 += bb0; xg01 += bb0;
        xg10 += bb1; xg11 += bb1;
    } else {
        px0 = g_xg + (size_t)b0 * Tt * Gg + j;          // pos j  = row r0
        px1 = px0 + (size_t)Tt * Gg;                     // batch row b0+1
    }

    // Weights: k=[0,96) -> registers, k=[96,128) -> smem
    const float* wrow0 = Whh + r0 * Hh;
    const float* wrow1 = Whh + r1 * Hh;
    u64 w0[48], w1[48];
    #pragma unroll
    for (int q = 0; q < 48; q++) w0[q] = *(const u64*)(wrow0 + 2 * q);
    #pragma unroll
    for (int q = 0; q < 48; q++) w1[q] = *(const u64*)(wrow1 + 2 * q);
    #pragma unroll
    for (int q = 0; q < 8; q++) Wsm0[q * 256 + j] = *(const ulonglong2*)(wrow0 + 96 + 4 * q);
    #pragma unroll
    for (int q = 0; q < 8; q++) Wsm1[q * 256 + j] = *(const ulonglong2*)(wrow1 + 96 + 4 * q);
    if (j < 64) ((float4*)hb0)[j] = make_float4(0.f, 0.f, 0.f, 0.f);
    else if (j < 128) ((float4*)hb1)[j - 64] = make_float4(0.f, 0.f, 0.f, 0.f);
    __syncthreads();

    float c = 0.f;                       // cell state for (row p_, element e)
    const float sc  = 2.f - (float)p_;   // gate1 activation: tanh(p=0)/sigm(p=1)
    const float off = 1.f - (float)p_;
    const int   hidx = (e >> 1) * 4 + p_ * 2 + (e & 1);
    float* hs2p = DEC ? (g_hs2 + ((size_t)(b0 + p_) * Tt) * Hh + e) : (float*)nullptr;

    for (int t = 0; t < Tt; t++) {
        float g00, g01, g10, g11;
        if (DEC) { g00 = xg00; g01 = xg01; g10 = xg10; g11 = xg11; }
        else {
            const float* q0 = px0 + (size_t)t * Gg;
            const float* q1 = px1 + (size_t)t * Gg;
            g00 = __ldg(q0); g10 = __ldg(q0 + 256);
            g01 = __ldg(q1); g11 = __ldg(q1 + 256);
        }
        const ulonglong2* hp = (const ulonglong2*)((t & 1) ? hb1 : hb0);
        float* hw = (t & 1) ? hb0 : hb1;

        u64 a00 = 0, a01 = 0, a10 = 0, a11 = 0;
        #pragma unroll
        for (int q = 0; q < 48; q++) {
            ulonglong2 h4 = hp[q];
            fma2(a00, w0[q], h4.x); fma2(a01, w0[q], h4.y);
            fma2(a10, w1[q], h4.x); fma2(a11, w1[q], h4.y);
        }
        #pragma unroll
        for (int q = 0; q < 8; q++) {
            ulonglong2 h4a = hp[48 + 2 * q];
            ulonglong2 h4b = hp[49 + 2 * q];
            ulonglong2 wa = Wsm0[q * 256 + j];
            ulonglong2 wb = Wsm1[q * 256 + j];
            fma2(a00, wa.x, h4a.x); fma2(a00, wa.y, h4b.x);
            fma2(a01, wa.x, h4a.y); fma2(a01, wa.y, h4b.y);
            fma2(a10, wb.x, h4a.x); fma2(a10, wb.y, h4b.x);
            fma2(a11, wb.x, h4a.y); fma2(a11, wb.y, h4b.y);
        }
        // gate0 (i for p=0 / f for p=1): always sigmoid
        float v00 = sigm(lo2(a00) + hi2(a00) + g00);
        float v01 = sigm(lo2(a01) + hi2(a01) + g01);
        // gate1 (g for p=0 -> tanh via sigm(2x)*2-1 / o for p=1 -> sigm)
        float v10 = sigm((lo2(a10) + hi2(a10) + g10) * sc) * sc - off;
        float v11 = sigm((lo2(a11) + hi2(a11) + g11) * sc) * sc - off;

        // lane-pair exchange: (2e)=i,g  (2e+1)=f,o
        float x00 = __shfl_xor_sync(0xffffffffu, v00, 1);
        float x01 = __shfl_xor_sync(0xffffffffu, v01, 1);
        float x10 = __shfl_xor_sync(0xffffffffu, v10, 1);
        float x11 = __shfl_xor_sync(0xffffffffu, v11, 1);
        // p=0 combines batch row 0; p=1 combines batch row 1
        float iv = p_ ? x01 : v00;
        float fv = p_ ? v01 : x00;
        float gv = p_ ? x11 : v10;
        float ov = p_ ? v11 : x10;
        c = fv * c + iv * gv;
        float h = ov * tanh_f(c);
        hw[hidx] = h;
        if (DEC) hs2p[(size_t)t * Hh] = h;
        __syncthreads();
    }

    if (!DEC) {
        // h_last lives in hb0 (t=511 wrote buffer 0). encoded = h@Wl^T + bl.
        if (j < 128) {
            int rr = j >> 6, l = j & 63;
            const float* wlr = Wl + l * Hh;
            float acc = __ldg(bl + l);
            #pragma unroll 16
            for (int k = 0; k < Hh; k++)
                acc += __ldg(wlr + k) * hb0[(k >> 1) * 4 + rr * 2 + (k & 1)];
            out[(b0 + rr) * LATD + l] = acc;
        }
    }
}

// ---------------------------------------------------------------------------
// Kernel D: decoded[b,t,d] = sum_h g_hs2[b,t,h]*dec_Wl[d,h] + dec_bl[d]
// grid 2048 x 256. W transposed to [kpair][d] u64 layout (conflict-free);
// h read as u64 broadcast; packed-f32x2 MACs.
// ---------------------------------------------------------------------------
__global__ __launch_bounds__(256) void out_kernel(
    const float* __restrict__ Wl, const float* __restrict__ bl,
    float* __restrict__ out)
{
    __shared__ __align__(16) float hrow[64 * 128];   // 32 KB
    __shared__ __align__(16) u64 wlT2[64 * 32];      // 16 KB : [kp][d] pairs
    const int t = threadIdx.x;
    const size_t row0 = (size_t)blockIdx.x * 64;

    {
        const float4* src = (const float4*)(g_hs2 + row0 * Hh);
        float4* dst = (float4*)hrow;
        #pragma unroll
        for (int i = t; i < 64 * 128 / 4; i += 256) dst[i] = src[i];
        float* wf = (float*)wlT2;
        for (int i = t; i < 32 * 128; i += 256) {
            int d = i >> 7, k = i & 127;
            wf[(k >> 1) * 64 + d * 2 + (k & 1)] = Wl[i];
        }
    }
    __syncthreads();

    const int d  = t & 31;
    const int rb = t >> 5;   // warp-uniform -> hrow reads broadcast
    u64 acc[8];
    #pragma unroll
    for (int q = 0; q < 8; q++) acc[q] = 0;

    const u64* wp = wlT2 + d;
    const u64* h2 = (const u64*)hrow;
    #pragma unroll 8
    for (int kp = 0; kp < 64; kp++) {
        u64 w = wp[(size_t)kp * 32];
        #pragma unroll
        for (int q = 0; q < 8; q++)
            fma2(acc[q], w, h2[(rb + q * 8) * 64 + kp]);
    }
    float bias = __ldg(bl + d);
    #pragma unroll
    for (int q = 0; q < 8; q++)
        out[(row0 + rb + q * 8) * DIN + d] = lo2(acc[q]) + hi2(acc[q]) + bias;
}

// ---------------------------------------------------------------------------
extern "C" void kernel_launch(void* const* d_in, const int* in_sizes, int n_in,
                              void* d_out, int out_size)
{
    const float* x        = (const float*)d_in[0];
    const float* enc_Wih  = (const float*)d_in[1];
    const float* enc_Whh  = (const float*)d_in[2];
    const float* enc_bih  = (const float*)d_in[3];
    const float* enc_bhh  = (const float*)d_in[4];
    const float* enc_Wl   = (const float*)d_in[5];
    const float* enc_bl   = (const float*)d_in[6];
    const float* dec_Wih  = (const float*)d_in[7];
    const float* dec_Whh  = (const float*)d_in[8];
    const float* dec_bih  = (const float*)d_in[9];
    const float* dec_bhh  = (const float*)d_in[10];
    const float* dec_Wl   = (const float*)d_in[11];
    const float* dec_bl   = (const float*)d_in[12];
    float* out = (float*)d_out;

    cudaFuncSetAttribute((const void*)lstm_kernel<false>,
                         cudaFuncAttributeMaxDynamicSharedMemorySize, SMEM_BYTES);
    cudaFuncSetAttribute((const void*)lstm_kernel<true>,
                         cudaFuncAttributeMaxDynamicSharedMemorySize, SMEM_BYTES);

    // 1) input transform for encoder (permuted gate layout)
    xg_kernel<<<(Bsz * Tt) / 128, 512>>>(x, enc_Wih, enc_bih, enc_bhh);
    // 2) encoder recurrence + encoded projection (writes out[0 : 256*64))
    lstm_kernel<false><<<Bsz / 2, 256, SMEM_BYTES>>>(
        enc_Whh, nullptr, nullptr, nullptr, nullptr, enc_Wl, enc_bl, out);
    // 3) decoder recurrence (reads encoded from out, writes g_hs2)
    lstm_kernel<true><<<Bsz / 2, 256, SMEM_BYTES>>>(
        dec_Whh, dec_Wih, dec_bih, dec_bhh, out, nullptr, nullptr, nullptr);
    // 4) decoded projection (writes out[256*64 : end))
    out_kernel<<<(Bsz * Tt) / 64, 256>>>(dec_Wl, dec_bl, out + Bsz * LATD);
}